// round 5
// baseline (speedup 1.0000x reference)
#include <cuda_runtime.h>
#include <cuda_fp16.h>
#include <stdint.h>

// ---------------- problem constants ----------------
#define SEQ      2048
#define M_TOK    65536          // 32 * 2048 tokens
#define HIDDEN   512
#define VOCAB    1024
#define KDIM     512
#define BUCKETS  4096

// ---------------- scratch (no allocs allowed) ----------------
__device__ __half g_feat[(size_t)M_TOK * HIDDEN];   // 64 MB
__device__ __half g_hA  [(size_t)M_TOK * HIDDEN];   // 64 MB
__device__ __half g_hB  [(size_t)M_TOK * HIDDEN];   // 64 MB
__device__ __half g_w   [4 * HIDDEN * HIDDEN + VOCAB * HIDDEN]; // fp16 weights

// ---------------- hash constants (bit-exact vs reference) ----------------
__constant__ long long c_primes[24] = {
    2654435761LL, 2246822519LL, 3266489917LL, 2028178513LL, 1220703125LL,
    1610612741LL, 805306457LL,  402653189LL,  3674653429LL, 2860486313LL,
    1073676287LL, 2971215073LL, 1500450271LL, 3267000013LL, 2654435789LL,
    4049292737LL, 2246822531LL, 3266489927LL, 2028178519LL, 1220703133LL,
    1610612743LL, 805306459LL,  402653191LL,  3674653433LL};

// SKIP_PATTERNS generated per reference for NUM_TABLES=32
__constant__ int c_plen[32] = {1,1,1,1,1,1,1,1,
                               2,2,2,2,2,2,2,2,2,2,2,2,
                               3,3,3,3,3,3,3,3,
                               2,2,2,2};
__constant__ int c_poff[32][3] = {
    {1,0,0},{2,0,0},{3,0,0},{4,0,0},{5,0,0},{6,0,0},{7,0,0},{8,0,0},
    {1,2,0},{2,3,0},{3,4,0},{1,3,0},{2,4,0},{1,4,0},{1,5,0},{2,5,0},
    {3,5,0},{1,6,0},{2,6,0},{1,7,0},
    {1,2,3},{1,2,4},{1,3,5},{2,3,4},{1,2,5},{1,3,4},{2,4,6},{1,4,7},
    {1,8,0},{1,9,0},{1,10,0},{1,11,0}};

// ---------------- weight fp32 -> fp16 convert ----------------
__global__ void cvt_kernel(const float* __restrict__ src, __half* __restrict__ dst, int n4) {
    int i = blockIdx.x * blockDim.x + threadIdx.x;
    if (i < n4) {
        float4 v = reinterpret_cast<const float4*>(src)[i];
        __half2 lo = __floats2half2_rn(v.x, v.y);
        __half2 hi = __floats2half2_rn(v.z, v.w);
        reinterpret_cast<__half2*>(dst)[2 * i]     = lo;
        reinterpret_cast<__half2*>(dst)[2 * i + 1] = hi;
    }
}

// ---------------- feature / poly-hash kernel ----------------
// One warp per token. Lane i handles hash table i (8 dims) plus 8 floats of
// the 256-dim byte embedding row. chars arrives as int32 (harness dtype);
// reference semantics are int64, and since tokens < 1024 the widening to
// 64-bit inside the hash is exact.
__global__ void feat_kernel(const int* __restrict__ chars,
                            const float* __restrict__ byte_embed,
                            const float* __restrict__ hash_tables,
                            __half* __restrict__ feat) {
    int w    = (blockIdx.x * blockDim.x + threadIdx.x) >> 5;  // token id
    int lane = threadIdx.x & 31;
    if (w >= M_TOK) return;
    int s = w & (SEQ - 1);

    int c = chars[w];

    // ---- byte embedding: 256 floats -> fp16 ----
    {
        const float4* bsrc = reinterpret_cast<const float4*>(byte_embed + (size_t)c * 256) + lane * 2;
        float4 v0 = bsrc[0];
        float4 v1 = bsrc[1];
        __half2 o[4];
        o[0] = __floats2half2_rn(v0.x, v0.y);
        o[1] = __floats2half2_rn(v0.z, v0.w);
        o[2] = __floats2half2_rn(v1.x, v1.y);
        o[3] = __floats2half2_rn(v1.z, v1.w);
        reinterpret_cast<uint4*>(feat + (size_t)w * HIDDEN)[lane] = *reinterpret_cast<uint4*>(o);
    }

    // ---- hash table lane (bit-exact int64 math) ----
    {
        int tl = c_plen[lane];
        long long h = 0;
        #pragma unroll
        for (int k = 0; k < 3; k++) {
            if (k < tl) {
                int off = c_poff[lane][k];
                long long tok = (s >= off) ? (long long)chars[w - off] : 0LL;
                // wrapping int64 multiply (tok small, but keep exact semantics)
                h ^= (long long)((unsigned long long)tok *
                                 (unsigned long long)c_primes[(lane * 3 + k) % 24]);
            }
        }
        int idx_lo = (int)(h & (long long)(BUCKETS - 1));   // h >= 0 here
        long long sp = c_primes[(lane * 3 + tl) % 24];
        // wrapping int64 multiply, arithmetic shift — matches XLA int64 semantics
        long long prod = (long long)((unsigned long long)h * (unsigned long long)sp);
        long long h2 = h ^ (prod >> 16);
        // floored mod by power of two == bitwise AND (valid for negatives too)
        int idx_hi = (int)(h2 & (long long)(BUCKETS - 1));
        float frac = ((float)(int)((h >> 3) & 255LL) / 255.0f) * 0.4f;
        float a = 1.0f - frac;

        const float* tab = hash_tables + (size_t)lane * BUCKETS * 8;
        const float4* lo = reinterpret_cast<const float4*>(tab + (size_t)idx_lo * 8);
        const float4* hi = reinterpret_cast<const float4*>(tab + (size_t)idx_hi * 8);
        float4 l0 = lo[0], l1 = lo[1];
        float4 h0 = hi[0], h1 = hi[1];
        __half2 o[4];
        o[0] = __floats2half2_rn(l0.x * a + h0.x * frac, l0.y * a + h0.y * frac);
        o[1] = __floats2half2_rn(l0.z * a + h0.z * frac, l0.w * a + h0.w * frac);
        o[2] = __floats2half2_rn(l1.x * a + h1.x * frac, l1.y * a + h1.y * frac);
        o[3] = __floats2half2_rn(l1.z * a + h1.z * frac, l1.w * a + h1.w * frac);
        reinterpret_cast<uint4*>(feat + (size_t)w * HIDDEN + 256)[lane] = *reinterpret_cast<uint4*>(o);
    }
}

// ---------------- GEMM: C = act(A @ W^T + bias) [+ Res] ----------------
// A: [M, K] fp16 row-major; W: [N, K] fp16 row-major (== col-major K x N).
// BM=128 BN=128 BK=32, 256 threads (8 warps, 2x4), warp tile 64x32 via m16n8k16.
#define BM 128
#define BN 128
#define BK 32
#define SPAD 40   // padded row stride (halves): conflict-free ldmatrix

template<bool RELU, bool HASRES, typename OT>
__global__ __launch_bounds__(256) void gemm_kernel(
    const __half* __restrict__ A, const __half* __restrict__ W,
    const float* __restrict__ bias, const __half* __restrict__ Res,
    OT* __restrict__ C, int N) {

    __shared__ __align__(16) __half As[2][BM][SPAD];
    __shared__ __align__(16) __half Bs[2][BN][SPAD];

    const int tid  = threadIdx.x;
    const int wid  = tid >> 5;
    const int lane = tid & 31;
    const int wm   = wid & 1;        // 0..1  (64 rows each)
    const int wn   = wid >> 1;       // 0..3  (32 cols each)
    const int m0   = blockIdx.x * BM;
    const int n0   = blockIdx.y * BN;

    float acc[4][4][4];
    #pragma unroll
    for (int i = 0; i < 4; i++)
        #pragma unroll
        for (int j = 0; j < 4; j++)
            #pragma unroll
            for (int k = 0; k < 4; k++) acc[i][j][k] = 0.0f;

    // global -> shared (cp.async, 16B chunks), fully aligned, no predicates
    auto load_stage = [&](int stage, int k0) {
        #pragma unroll
        for (int it = 0; it < 2; it++) {
            int chunk = tid + it * 256;          // 0..511
            int r  = chunk >> 2;                 // row 0..127
            int cc = (chunk & 3) << 3;           // col 0,8,16,24
            const __half* ga = A + (size_t)(m0 + r) * KDIM + k0 + cc;
            uint32_t sa = (uint32_t)__cvta_generic_to_shared(&As[stage][r][cc]);
            asm volatile("cp.async.cg.shared.global [%0], [%1], 16;\n" :: "r"(sa), "l"(ga));
            const __half* gb = W + (size_t)(n0 + r) * KDIM + k0 + cc;
            uint32_t sb = (uint32_t)__cvta_generic_to_shared(&Bs[stage][r][cc]);
            asm volatile("cp.async.cg.shared.global [%0], [%1], 16;\n" :: "r"(sb), "l"(gb));
        }
        asm volatile("cp.async.commit_group;\n" ::: "memory");
    };

    load_stage(0, 0);
    const int NK = KDIM / BK;   // 16

    for (int kt = 0; kt < NK; kt++) {
        asm volatile("cp.async.wait_group 0;\n" ::: "memory");
        __syncthreads();
        if (kt + 1 < NK) load_stage((kt + 1) & 1, (kt + 1) * BK);
        const int st = kt & 1;

        #pragma unroll
        for (int kk = 0; kk < 2; kk++) {       // two k16 steps per BK=32
            uint32_t af[4][4];
            uint32_t bf[4][2];
            #pragma unroll
            for (int mt = 0; mt < 4; mt++) {
                const __half* p = &As[st][wm * 64 + mt * 16 + (lane & 15)]
                                        [kk * 16 + ((lane >> 4) << 3)];
                uint32_t ad = (uint32_t)__cvta_generic_to_shared(p);
                asm volatile("ldmatrix.sync.aligned.m8n8.x4.shared.b16 {%0,%1,%2,%3}, [%4];\n"
                             : "=r"(af[mt][0]), "=r"(af[mt][1]), "=r"(af[mt][2]), "=r"(af[mt][3])
                             : "r"(ad));
            }
            #pragma unroll
            for (int np = 0; np < 2; np++) {
                int blk = lane >> 3, r = lane & 7;
                const __half* p = &Bs[st][wn * 32 + np * 16 + ((blk >> 1) << 3) + r]
                                        [kk * 16 + ((blk & 1) << 3)];
                uint32_t ad = (uint32_t)__cvta_generic_to_shared(p);
                asm volatile("ldmatrix.sync.aligned.m8n8.x4.shared.b16 {%0,%1,%2,%3}, [%4];\n"
                             : "=r"(bf[np * 2][0]), "=r"(bf[np * 2][1]),
                               "=r"(bf[np * 2 + 1][0]), "=r"(bf[np * 2 + 1][1])
                             : "r"(ad));
            }
            #pragma unroll
            for (int mt = 0; mt < 4; mt++)
                #pragma unroll
                for (int nt = 0; nt < 4; nt++)
                    asm volatile(
                        "mma.sync.aligned.m16n8k16.row.col.f32.f16.f16.f32 "
                        "{%0,%1,%2,%3}, {%4,%5,%6,%7}, {%8,%9}, {%0,%1,%2,%3};\n"
                        : "+f"(acc[mt][nt][0]), "+f"(acc[mt][nt][1]),
                          "+f"(acc[mt][nt][2]), "+f"(acc[mt][nt][3])
                        : "r"(af[mt][0]), "r"(af[mt][1]), "r"(af[mt][2]), "r"(af[mt][3]),
                          "r"(bf[nt][0]), "r"(bf[nt][1]));
        }
        __syncthreads();
    }

    // ---- epilogue: bias (+relu) (+residual) ----
    #pragma unroll
    for (int nt = 0; nt < 4; nt++) {
        int col = n0 + wn * 32 + nt * 8 + ((lane & 3) << 1);
        float b0 = bias[col], b1 = bias[col + 1];
        #pragma unroll
        for (int mt = 0; mt < 4; mt++) {
            int row = m0 + wm * 64 + mt * 16 + (lane >> 2);
            #pragma unroll
            for (int half_ = 0; half_ < 2; half_++) {
                int r = row + half_ * 8;
                float v0 = acc[mt][nt][half_ * 2 + 0] + b0;
                float v1 = acc[mt][nt][half_ * 2 + 1] + b1;
                if (RELU) { v0 = fmaxf(v0, 0.0f); v1 = fmaxf(v1, 0.0f); }
                if (HASRES) {
                    __half2 rr = *reinterpret_cast<const __half2*>(&Res[(size_t)r * N + col]);
                    float2 rf = __half22float2(rr);
                    v0 += rf.x; v1 += rf.y;
                }
                if (sizeof(OT) == 2) {
                    *reinterpret_cast<__half2*>((__half*)C + (size_t)r * N + col) =
                        __floats2half2_rn(v0, v1);
                } else {
                    *reinterpret_cast<float2*>((float*)C + (size_t)r * N + col) =
                        make_float2(v0, v1);
                }
            }
        }
    }
}

// ---------------- launch ----------------
extern "C" void kernel_launch(void* const* d_in, const int* in_sizes, int n_in,
                              void* d_out, int out_size) {
    const int* chars           = (const int*)d_in[0];     // int32 per harness dtype set
    const float* byte_embed    = (const float*)d_in[1];
    const float* hash_tables   = (const float*)d_in[2];
    const float* w_in          = (const float*)d_in[3];
    const float* b_in          = (const float*)d_in[4];
    const float* mlp_ws        = (const float*)d_in[5];
    const float* mlp_bs        = (const float*)d_in[6];
    const float* w_out         = (const float*)d_in[7];
    const float* b_out         = (const float*)d_in[8];
    float* out                 = (float*)d_out;

    void *pf, *pa, *pb, *pw;
    cudaGetSymbolAddress(&pf, g_feat);
    cudaGetSymbolAddress(&pa, g_hA);
    cudaGetSymbolAddress(&pb, g_hB);
    cudaGetSymbolAddress(&pw, g_w);
    __half* feat = (__half*)pf;
    __half* hA   = (__half*)pa;
    __half* hB   = (__half*)pb;
    __half* gw   = (__half*)pw;

    // weights -> fp16
    {
        int n4;
        n4 = (HIDDEN * HIDDEN) / 4;
        cvt_kernel<<<(n4 + 255) / 256, 256>>>(w_in, gw, n4);
        n4 = (3 * HIDDEN * HIDDEN) / 4;
        cvt_kernel<<<(n4 + 255) / 256, 256>>>(mlp_ws, gw + HIDDEN * HIDDEN, n4);
        n4 = (VOCAB * HIDDEN) / 4;
        cvt_kernel<<<(n4 + 255) / 256, 256>>>(w_out, gw + 4 * HIDDEN * HIDDEN, n4);
    }

    // features
    feat_kernel<<<M_TOK / 8, 256>>>(chars, byte_embed, hash_tables, feat);

    dim3 blk(256);
    dim3 g512(M_TOK / BM, HIDDEN / BN);   // (512, 4)
    dim3 g1024(M_TOK / BM, VOCAB / BN);   // (512, 8)
    const int WW = HIDDEN * HIDDEN;

    // h = relu(feat @ w_in^T + b_in)
    gemm_kernel<true, false, __half><<<g512, blk>>>(feat, gw, b_in, nullptr, hA, HIDDEN);
    // residual blocks: h = relu(h @ W^T + b) + h
    gemm_kernel<true, true, __half><<<g512, blk>>>(hA, gw + 1 * WW, mlp_bs + 0 * HIDDEN, hA, hB, HIDDEN);
    gemm_kernel<true, true, __half><<<g512, blk>>>(hB, gw + 2 * WW, mlp_bs + 1 * HIDDEN, hB, hA, HIDDEN);
    gemm_kernel<true, true, __half><<<g512, blk>>>(hA, gw + 3 * WW, mlp_bs + 2 * HIDDEN, hA, hB, HIDDEN);
    // logits = h @ w_out^T + b_out  (fp32 out, no relu, no residual)
    gemm_kernel<false, false, float><<<g1024, blk>>>(hB, gw + 4 * WW, b_out, nullptr, out, VOCAB);
}